// round 10
// baseline (speedup 1.0000x reference)
#include <cuda_runtime.h>
#include <cuda_bf16.h>

#define N       512
#define D       2048
#define LDIM    128
#define PARTS   8
#define SPLITK  4
#define KSPLIT  (D / SPLITK)       // 512
#define KC      32                 // k per pipeline chunk
#define NCH     (KSPLIT / KC)      // 16
#define NTILES  36
#define MARGIN  0.3f

#define SM_STRIDE 80                       // bytes per smem row (32 bf16 + 8 pad)
#define TILE_B    (64 * SM_STRIDE)         // 5120
#define STAGE_B   (4 * TILE_B)             // 20480 (Ah, Al, Bh, Bl)

// ---------------- device scratch (static allocation only) ----------------
__device__ float g_sq[N];
__device__ float g_gram[SPLITK][N * N];
__device__ float g_gl[N];
__device__ float g_ll[N];
__device__ int   g_cnt = 0;

// symmetric tile list: all (mt, nt) with mt <= nt on the 8x8 grid of 64x64 tiles
__constant__ unsigned char c_mt[NTILES] = {
    0,0,0,0,0,0,0,0, 1,1,1,1,1,1,1, 2,2,2,2,2,2, 3,3,3,3,3, 4,4,4,4, 5,5,5, 6,6, 7};
__constant__ unsigned char c_nt[NTILES] = {
    0,1,2,3,4,5,6,7, 1,2,3,4,5,6,7, 2,3,4,5,6,7, 3,4,5,6,7, 4,5,6,7, 5,6,7, 6,7, 7};

// ---------------- helpers ----------------
__device__ __forceinline__ unsigned s2u(const void* p) {
    unsigned a;
    asm("{ .reg .u64 t; cvta.to.shared.u64 t, %1; cvt.u32.u64 %0, t; }"
        : "=r"(a) : "l"(p));
    return a;
}
__device__ __forceinline__ void ldm4(unsigned* f, unsigned saddr) {
    asm volatile("ldmatrix.sync.aligned.m8n8.x4.shared.b16 {%0,%1,%2,%3}, [%4];"
                 : "=r"(f[0]), "=r"(f[1]), "=r"(f[2]), "=r"(f[3]) : "r"(saddr));
}
__device__ __forceinline__ void mma_bf16(float* d, const unsigned* a,
                                         unsigned b0, unsigned b1) {
    asm volatile(
        "mma.sync.aligned.m16n8k16.row.col.f32.bf16.bf16.f32 "
        "{%0,%1,%2,%3}, {%4,%5,%6,%7}, {%8,%9}, {%0,%1,%2,%3};"
        : "+f"(d[0]), "+f"(d[1]), "+f"(d[2]), "+f"(d[3])
        : "r"(a[0]), "r"(a[1]), "r"(a[2]), "r"(a[3]), "r"(b0), "r"(b1));
}

// convert 8 fp32 -> 16B hi bf16 + 16B lo bf16, store to smem tiles
__device__ __forceinline__ void cvt_store(char* tH, char* tL, unsigned off,
                                          float4 v0, float4 v1) {
    float f[8] = {v0.x, v0.y, v0.z, v0.w, v1.x, v1.y, v1.z, v1.w};
    unsigned hw[8], lw[8];
#pragma unroll
    for (int i = 0; i < 8; i++) {
        __nv_bfloat16 h = __float2bfloat16_rn(f[i]);
        __nv_bfloat16 l = __float2bfloat16_rn(f[i] - __bfloat162float(h));
        hw[i] = (unsigned)__bfloat16_as_ushort(h);
        lw[i] = (unsigned)__bfloat16_as_ushort(l);
    }
    uint4 H = make_uint4(hw[0] | (hw[1] << 16), hw[2] | (hw[3] << 16),
                         hw[4] | (hw[5] << 16), hw[6] | (hw[7] << 16));
    uint4 L = make_uint4(lw[0] | (lw[1] << 16), lw[2] | (lw[3] << 16),
                         lw[4] | (lw[5] << 16), lw[6] | (lw[7] << 16));
    *reinterpret_cast<uint4*>(tH + off) = H;
    *reinterpret_cast<uint4*>(tL + off) = L;
}

// ---------------- kernel 1: fused Gram (mma.sync bf16 3-term) + row norms ----
// grid (37, 4): x<36 -> symmetric 64x64 tile, x==36 -> norms for 128 rows.
// 148 CTAs = 148 SMs, one wave. fp32 loaded directly; hi/lo split in-kernel.
__global__ void __launch_bounds__(256, 1)
gram_fused_kernel(const float* __restrict__ X) {
    const int split = blockIdx.y;

    if (blockIdx.x == NTILES) {
        // exact fp32 norms for rows split*128 .. split*128+127 (2 threads/row)
        const int row  = split * 128 + (threadIdx.x >> 1);
        const int half = threadIdx.x & 1;
        const float4* x4 = reinterpret_cast<const float4*>(X + (size_t)row * D)
                           + half * (D / 8);
        float s = 0.0f;
#pragma unroll 8
        for (int k = 0; k < D / 8; k++) {
            float4 v = x4[k];
            s += v.x * v.x + v.y * v.y + v.z * v.z + v.w * v.w;
        }
        s += __shfl_xor_sync(0xffffffffu, s, 1);
        if (half == 0) g_sq[row] = s;
        return;
    }

    __shared__ __align__(16) char sm[2 * STAGE_B];   // 40 KB, ping-pong stages
    const unsigned smu = s2u(sm);

    const int tid  = threadIdx.x;
    const int wid  = tid >> 5;
    const int lane = tid & 31;
    const int wr   = wid & 3;           // warp row -> m offset wr*16
    const int wc   = wid >> 2;          // warp col -> n offset wc*32
    const int m0   = (int)c_mt[blockIdx.x] * 64;
    const int n0   = (int)c_nt[blockIdx.x] * 64;
    const int kz   = split * KSPLIT;

    // per-thread fill slot: row lr (0..63), 8-float k-group lch (0..3)
    const int lr  = tid >> 2;
    const int lch = tid & 3;
    const unsigned dst_off = (unsigned)(lr * SM_STRIDE + lch * 16);
    const float* Am = X + (size_t)(m0 + lr) * D + kz + lch * 8;
    const float* Bn = X + (size_t)(n0 + lr) * D + kz + lch * 8;

    // ldmatrix per-lane offsets (bytes, within a stage)
    const unsigned aOff = (unsigned)((wr * 16 + (lane & 15)) * SM_STRIDE
                                     + ((lane >> 4) << 4));
    unsigned bOff[2];
#pragma unroll
    for (int p = 0; p < 2; p++)
        bOff[p] = (unsigned)((wc * 32 + p * 16 + ((lane >> 4) & 1) * 8 + (lane & 7))
                             * SM_STRIDE + ((lane >> 3) & 1) * 16);

    float acc[4][4];
#pragma unroll
    for (int nt = 0; nt < 4; nt++)
#pragma unroll
        for (int e = 0; e < 4; e++) acc[nt][e] = 0.0f;

    // register staging for one chunk (A: 2 float4, B: 2 float4)
    float4 ra0, ra1, rb0, rb1;

    // prologue: chunk 0 -> buf0; load chunk 1 into regs
    ra0 = *reinterpret_cast<const float4*>(Am);
    ra1 = *reinterpret_cast<const float4*>(Am + 4);
    rb0 = *reinterpret_cast<const float4*>(Bn);
    rb1 = *reinterpret_cast<const float4*>(Bn + 4);
    {
        char* b0 = sm;
        cvt_store(b0,              b0 + TILE_B,     dst_off, ra0, ra1);
        cvt_store(b0 + 2 * TILE_B, b0 + 3 * TILE_B, dst_off, rb0, rb1);
    }
    ra0 = *reinterpret_cast<const float4*>(Am + KC);
    ra1 = *reinterpret_cast<const float4*>(Am + KC + 4);
    rb0 = *reinterpret_cast<const float4*>(Bn + KC);
    rb1 = *reinterpret_cast<const float4*>(Bn + KC + 4);
    __syncthreads();

#pragma unroll 1
    for (int c = 0; c < NCH; c++) {
        const unsigned st = smu + (c & 1) * STAGE_B;
#pragma unroll
        for (int s16 = 0; s16 < 2; s16++) {
            unsigned ah[4], al[4], bh[8], bl[8];
            const unsigned ka = st + aOff + s16 * 32;
            ldm4(ah, ka);
            ldm4(al, ka + TILE_B);
#pragma unroll
            for (int p = 0; p < 2; p++) {
                const unsigned kb = st + bOff[p] + s16 * 32;
                ldm4(&bh[p * 4], kb + 2 * TILE_B);
                ldm4(&bl[p * 4], kb + 3 * TILE_B);
            }
#pragma unroll
            for (int nt = 0; nt < 4; nt++) {
                const int bi = (nt >> 1) * 4 + (nt & 1) * 2;
                mma_bf16(acc[nt], ah, bh[bi], bh[bi + 1]);  // hh
                mma_bf16(acc[nt], ah, bl[bi], bl[bi + 1]);  // h*l
                mma_bf16(acc[nt], al, bh[bi], bh[bi + 1]);  // l*h
            }
        }

        if (c + 1 < NCH) {   // convert chunk c+1 from regs into the other stage
            char* nb = sm + ((c + 1) & 1) * STAGE_B;
            cvt_store(nb,              nb + TILE_B,     dst_off, ra0, ra1);
            cvt_store(nb + 2 * TILE_B, nb + 3 * TILE_B, dst_off, rb0, rb1);
        }
        if (c + 2 < NCH) {   // prefetch chunk c+2 into regs
            const int gk = (c + 2) * KC;
            ra0 = *reinterpret_cast<const float4*>(Am + gk);
            ra1 = *reinterpret_cast<const float4*>(Am + gk + 4);
            rb0 = *reinterpret_cast<const float4*>(Bn + gk);
            rb1 = *reinterpret_cast<const float4*>(Bn + gk + 4);
        }
        __syncthreads();
    }

    // epilogue: direct store + mirrored store for off-diagonal tiles
    float* out = g_gram[split];
    const int rbase = m0 + wr * 16 + (lane >> 2);
    const bool mirror = (m0 != n0);
#pragma unroll
    for (int nt = 0; nt < 4; nt++) {
        const int col = n0 + wc * 32 + nt * 8 + (lane & 3) * 2;
        *reinterpret_cast<float2*>(&out[(size_t)rbase * N + col]) =
            make_float2(acc[nt][0], acc[nt][1]);
        *reinterpret_cast<float2*>(&out[(size_t)(rbase + 8) * N + col]) =
            make_float2(acc[nt][2], acc[nt][3]);
        if (mirror) {
            out[(size_t)col * N + rbase]           = acc[nt][0];
            out[(size_t)(col + 1) * N + rbase]     = acc[nt][1];
            out[(size_t)col * N + rbase + 8]       = acc[nt][2];
            out[(size_t)(col + 1) * N + rbase + 8] = acc[nt][3];
        }
    }
}

// ---------------- kernel 2: mining + local DTW + last-block final reduction ----
__global__ void __launch_bounds__(128)
mine_local_kernel(const void* __restrict__ targets_raw,
                  const float* __restrict__ LF,
                  float* __restrict__ out) {
    const int i = blockIdx.x;
    const int t = threadIdx.x;

    // dtype detection: targets = j//4 -> word[5] nonzero for int32 layout, 0 for int64.
    const int* ip = reinterpret_cast<const int*>(targets_raw);
    const int stride = (ip[5] == 0) ? 2 : 1;

    const int   ti  = ip[(size_t)i * stride];
    const float sqi = g_sq[i];

    const int j0 = t * 4;
    float4 g = make_float4(0.f, 0.f, 0.f, 0.f);
#pragma unroll
    for (int s = 0; s < SPLITK; s++) {
        float4 v = *reinterpret_cast<const float4*>(&g_gram[s][(size_t)i * N + j0]);
        g.x += v.x; g.y += v.y; g.z += v.z; g.w += v.w;
    }

    float apv = -3.0e38f; int apj = N;
    float anv =  3.0e38f; int anj = N;
    float gv[4] = {g.x, g.y, g.z, g.w};
#pragma unroll
    for (int u = 0; u < 4; u++) {
        int j = j0 + u;
        float d = sqrtf(fmaxf(sqi + g_sq[j] - 2.0f * gv[u], 1e-12f));
        if (ip[(size_t)j * stride] == ti) {
            if (d > apv) { apv = d; apj = j; }   // strict > keeps first index
        } else {
            if (d < anv) { anv = d; anj = j; }
        }
    }
#pragma unroll
    for (int o = 16; o > 0; o >>= 1) {
        float v = __shfl_down_sync(0xffffffffu, apv, o);
        int   j = __shfl_down_sync(0xffffffffu, apj, o);
        if (v > apv || (v == apv && j < apj)) { apv = v; apj = j; }
        v = __shfl_down_sync(0xffffffffu, anv, o);
        j = __shfl_down_sync(0xffffffffu, anj, o);
        if (v < anv || (v == anv && j < anj)) { anv = v; anj = j; }
    }
    __shared__ float sapv[4], sanv[4];
    __shared__ int   sapj[4], sanj[4];
    __shared__ int   s_pi, s_ni;
    if ((t & 31) == 0) {
        int w = t >> 5;
        sapv[w] = apv; sapj[w] = apj;
        sanv[w] = anv; sanj[w] = anj;
    }
    __syncthreads();
    if (t == 0) {
        for (int w = 1; w < 4; w++) {
            if (sapv[w] > apv || (sapv[w] == apv && sapj[w] < apj)) { apv = sapv[w]; apj = sapj[w]; }
            if (sanv[w] < anv || (sanv[w] == anv && sanj[w] < anj)) { anv = sanv[w]; anj = sanj[w]; }
        }
        s_pi = apj;
        s_ni = anj;
        g_gl[i] = fmaxf(0.0f, MARGIN + apv - anv);
    }
    __syncthreads();

    // ---- local aligned (DTW) loss ----
    __shared__ float sa[PARTS][LDIM + 4];
    __shared__ float sb[PARTS][LDIM + 4];
    __shared__ float sc[PARTS][LDIM + 4];
    __shared__ float dA[PARTS][PARTS];
    __shared__ float dB[PARTS][PARTS];
    __shared__ float res[2];

    const float* A = LF + (size_t)i    * (LDIM * PARTS);
    const float* B = LF + (size_t)s_pi * (LDIM * PARTS);
    const float* C = LF + (size_t)s_ni * (LDIM * PARTS);

    for (int idx = t; idx < LDIM * PARTS; idx += 128) {
        int d = idx >> 3, p = idx & 7;
        sa[p][d] = A[idx];
        sb[p][d] = B[idx];
        sc[p][d] = C[idx];
    }
    __syncthreads();

    if (t < 64) {
        const int p = t >> 3, q = t & 7;
        float s1 = 0.0f, s2 = 0.0f;
#pragma unroll 8
        for (int d = 0; d < LDIM; d++) {
            float av = sa[p][d];
            float x = av - sb[q][d]; s1 += x * x;
            float y = av - sc[q][d]; s2 += y * y;
        }
        dA[p][q] = tanhf(0.5f * sqrtf(fmaxf(s1, 1e-12f)));
        dB[p][q] = tanhf(0.5f * sqrtf(fmaxf(s2, 1e-12f)));
    }
    __syncthreads();

    if (t < 2) {
        float (*dm)[PARTS] = (t == 0) ? dA : dB;
        float prev[PARTS];
        prev[0] = 0.0f;
#pragma unroll
        for (int j = 1; j < PARTS; j++) prev[j] = 1e9f;
#pragma unroll
        for (int r = 0; r < PARTS; r++) {
            float left = 1e9f;
#pragma unroll
            for (int j = 0; j < PARTS; j++) {
                float cur = dm[r][j] + fminf(prev[j], left);
                prev[j] = cur;
                left = cur;
            }
        }
        res[t] = prev[PARTS - 1];
    }
    __syncthreads();

    // ---- last-block final reduction (threadfence + counter pattern) ----
    __shared__ int s_last;
    if (t == 0) {
        g_ll[i] = fmaxf(0.0f, MARGIN + res[0] - res[1]);
        __threadfence();
        int old = atomicAdd(&g_cnt, 1);
        s_last = (old == N - 1) ? 1 : 0;
    }
    __syncthreads();
    if (s_last) {
        if (t == 0) g_cnt = 0;       // reset for next graph replay
        float a = 0.0f, b = 0.0f;
#pragma unroll
        for (int j = t; j < N; j += 128) {
            a += g_gl[j];
            b += g_ll[j];
        }
#pragma unroll
        for (int o = 16; o > 0; o >>= 1) {
            a += __shfl_down_sync(0xffffffffu, a, o);
            b += __shfl_down_sync(0xffffffffu, b, o);
        }
        __shared__ float wa[4], wb[4];
        if ((t & 31) == 0) { wa[t >> 5] = a; wb[t >> 5] = b; }
        __syncthreads();
        if (t == 0) {
            a = wa[0] + wa[1] + wa[2] + wa[3];
            b = wb[0] + wb[1] + wb[2] + wb[3];
            out[0] = a * (1.0f / N);
            out[1] = b * (1.0f / N);
        }
    }
}

// ---------------- launch ----------------
extern "C" void kernel_launch(void* const* d_in, const int* in_sizes, int n_in,
                              void* d_out, int out_size) {
    const float* X  = (const float*)d_in[0];
    const void*  TG = d_in[1];
    const float* LF = (const float*)d_in[2];
    float* out = (float*)d_out;

    gram_fused_kernel<<<dim3(NTILES + 1, SPLITK), 256>>>(X);
    mine_local_kernel<<<N, 128>>>(TG, LF, out);
}

// round 11
// speedup vs baseline: 1.6927x; 1.6927x over previous
#include <cuda_runtime.h>
#include <cuda_bf16.h>

#define N       512
#define D       2048
#define LDIM    128
#define PARTS   8
#define SPLITK  4
#define KSPLIT  (D / SPLITK)       // 512
#define KC      32                 // k per pipeline chunk
#define NCH     (KSPLIT / KC)      // 16
#define NTILES  36
#define MARGIN  0.3f

#define SM_STRIDE 80                       // bytes per smem row (32 bf16 + 8 pad)
#define TILE_B    (64 * SM_STRIDE)         // 5120
#define STAGE_B   (4 * TILE_B)             // 20480 (Ah, Al, Bh, Bl)

#define ML_BLOCKS (N / 2)                  // 256 blocks, 2 warps = 2 samples each
#define LSTRIDE   (LDIM + 4)               // padded smem row for parts

// ---------------- device scratch (static allocation only) ----------------
__device__ float          g_sq[N];
__device__ __nv_bfloat16  g_xh[N * D];
__device__ __nv_bfloat16  g_xl[N * D];
__device__ float          g_gram[SPLITK][N * N];
__device__ float          g_gl[N];
__device__ float          g_ll[N];
__device__ int            g_cnt = 0;

// symmetric tile list: all (mt, nt) with mt <= nt on the 8x8 grid of 64x64 tiles
__constant__ unsigned char c_mt[NTILES] = {
    0,0,0,0,0,0,0,0, 1,1,1,1,1,1,1, 2,2,2,2,2,2, 3,3,3,3,3, 4,4,4,4, 5,5,5, 6,6, 7};
__constant__ unsigned char c_nt[NTILES] = {
    0,1,2,3,4,5,6,7, 1,2,3,4,5,6,7, 2,3,4,5,6,7, 3,4,5,6,7, 4,5,6,7, 5,6,7, 6,7, 7};

// ---------------- helpers ----------------
__device__ __forceinline__ unsigned s2u(const void* p) {
    unsigned a;
    asm("{ .reg .u64 t; cvta.to.shared.u64 t, %1; cvt.u32.u64 %0, t; }"
        : "=r"(a) : "l"(p));
    return a;
}
__device__ __forceinline__ void cpa16(unsigned saddr, const void* gaddr) {
    asm volatile("cp.async.cg.shared.global [%0], [%1], 16;"
                 :: "r"(saddr), "l"(gaddr) : "memory");
}
__device__ __forceinline__ void ldm4(unsigned* f, unsigned saddr) {
    asm volatile("ldmatrix.sync.aligned.m8n8.x4.shared.b16 {%0,%1,%2,%3}, [%4];"
                 : "=r"(f[0]), "=r"(f[1]), "=r"(f[2]), "=r"(f[3]) : "r"(saddr));
}
__device__ __forceinline__ void mma_bf16(float* d, const unsigned* a,
                                         unsigned b0, unsigned b1) {
    asm volatile(
        "mma.sync.aligned.m16n8k16.row.col.f32.bf16.bf16.f32 "
        "{%0,%1,%2,%3}, {%4,%5,%6,%7}, {%8,%9}, {%0,%1,%2,%3};"
        : "+f"(d[0]), "+f"(d[1]), "+f"(d[2]), "+f"(d[3])
        : "r"(a[0]), "r"(a[1]), "r"(a[2]), "r"(a[3]), "r"(b0), "r"(b1));
}

// ---------------- kernel 1: fp32 -> bf16 hi/lo split + row norms ----------------
__global__ void __launch_bounds__(256)
convert_kernel(const float* __restrict__ X) {
    const int row = blockIdx.x;
    const int t   = threadIdx.x;
    const float4* x4 = reinterpret_cast<const float4*>(X + (size_t)row * D);
    __nv_bfloat162* xh2 = reinterpret_cast<__nv_bfloat162*>(g_xh + (size_t)row * D);
    __nv_bfloat162* xl2 = reinterpret_cast<__nv_bfloat162*>(g_xl + (size_t)row * D);

    float s = 0.0f;
#pragma unroll
    for (int it = 0; it < 2; it++) {
        int idx = t + 256 * it;          // float4 index, 0..511
        float4 v = x4[idx];
        s += v.x * v.x + v.y * v.y + v.z * v.z + v.w * v.w;
        __nv_bfloat16 hx = __float2bfloat16_rn(v.x);
        __nv_bfloat16 hy = __float2bfloat16_rn(v.y);
        __nv_bfloat16 hz = __float2bfloat16_rn(v.z);
        __nv_bfloat16 hw = __float2bfloat16_rn(v.w);
        __nv_bfloat16 lx = __float2bfloat16_rn(v.x - __bfloat162float(hx));
        __nv_bfloat16 ly = __float2bfloat16_rn(v.y - __bfloat162float(hy));
        __nv_bfloat16 lz = __float2bfloat16_rn(v.z - __bfloat162float(hz));
        __nv_bfloat16 lw = __float2bfloat16_rn(v.w - __bfloat162float(hw));
        xh2[idx * 2]     = __nv_bfloat162(hx, hy);
        xh2[idx * 2 + 1] = __nv_bfloat162(hz, hw);
        xl2[idx * 2]     = __nv_bfloat162(lx, ly);
        xl2[idx * 2 + 1] = __nv_bfloat162(lz, lw);
    }
#pragma unroll
    for (int o = 16; o > 0; o >>= 1) s += __shfl_down_sync(0xffffffffu, s, o);
    __shared__ float ws[8];
    if ((t & 31) == 0) ws[t >> 5] = s;
    __syncthreads();
    if (t < 8) {
        s = ws[t];
#pragma unroll
        for (int o = 4; o > 0; o >>= 1) s += __shfl_down_sync(0xffu, s, o);
        if (t == 0) g_sq[row] = s;
    }
}

// ---------------- kernel 2: Gram via mma.sync bf16, 3-term split (R9, proven) ----
__global__ void __launch_bounds__(256, 1)
gram_mma_kernel() {
    __shared__ __align__(16) char sm[2 * STAGE_B];   // 40 KB
    const unsigned smu = s2u(sm);

    const int tid  = threadIdx.x;
    const int wid  = tid >> 5;
    const int lane = tid & 31;
    const int wr   = wid & 3;
    const int wc   = wid >> 2;
    const int m0   = (int)c_mt[blockIdx.x] * 64;
    const int n0   = (int)c_nt[blockIdx.x] * 64;
    const int split = blockIdx.y;
    const int kz   = split * KSPLIT;

    const int lr  = tid >> 2;
    const int lch = tid & 3;
    const unsigned dst_off = (unsigned)(lr * SM_STRIDE + lch * 16);
    const size_t   src_off = (size_t)lr * D + lch * 8;
    const __nv_bfloat16* Amh = g_xh + (size_t)m0 * D + src_off;
    const __nv_bfloat16* Aml = g_xl + (size_t)m0 * D + src_off;
    const __nv_bfloat16* Bnh = g_xh + (size_t)n0 * D + src_off;
    const __nv_bfloat16* Bnl = g_xl + (size_t)n0 * D + src_off;

    const unsigned aOff = (unsigned)((wr * 16 + (lane & 15)) * SM_STRIDE
                                     + ((lane >> 4) << 4));
    unsigned bOff[2];
#pragma unroll
    for (int p = 0; p < 2; p++)
        bOff[p] = (unsigned)((wc * 32 + p * 16 + ((lane >> 4) & 1) * 8 + (lane & 7))
                             * SM_STRIDE + ((lane >> 3) & 1) * 16);

    float acc[4][4];
#pragma unroll
    for (int nt = 0; nt < 4; nt++)
#pragma unroll
        for (int e = 0; e < 4; e++) acc[nt][e] = 0.0f;

#pragma unroll
    for (int c = 0; c < 2; c++) {
        const unsigned sb = smu + c * STAGE_B + dst_off;
        const size_t   gk = kz + c * KC;
        cpa16(sb,              Amh + gk);
        cpa16(sb + TILE_B,     Aml + gk);
        cpa16(sb + 2 * TILE_B, Bnh + gk);
        cpa16(sb + 3 * TILE_B, Bnl + gk);
        asm volatile("cp.async.commit_group;" ::: "memory");
    }

#pragma unroll 1
    for (int c = 0; c < NCH; c++) {
        if (c < NCH - 1) asm volatile("cp.async.wait_group 1;" ::: "memory");
        else             asm volatile("cp.async.wait_group 0;" ::: "memory");
        __syncthreads();

        const unsigned st = smu + (c & 1) * STAGE_B;
#pragma unroll
        for (int s16 = 0; s16 < 2; s16++) {
            unsigned ah[4], al[4], bh[8], bl[8];
            const unsigned ka = st + aOff + s16 * 32;
            ldm4(ah, ka);
            ldm4(al, ka + TILE_B);
#pragma unroll
            for (int p = 0; p < 2; p++) {
                const unsigned kb = st + bOff[p] + s16 * 32;
                ldm4(&bh[p * 4], kb + 2 * TILE_B);
                ldm4(&bl[p * 4], kb + 3 * TILE_B);
            }
#pragma unroll
            for (int nt = 0; nt < 4; nt++) {
                const int bi = (nt >> 1) * 4 + (nt & 1) * 2;
                mma_bf16(acc[nt], ah, bh[bi], bh[bi + 1]);
                mma_bf16(acc[nt], ah, bl[bi], bl[bi + 1]);
                mma_bf16(acc[nt], al, bh[bi], bh[bi + 1]);
            }
        }
        __syncthreads();

        if (c + 2 < NCH) {
            const unsigned sb = smu + (c & 1) * STAGE_B + dst_off;
            const size_t   gk = kz + (size_t)(c + 2) * KC;
            cpa16(sb,              Amh + gk);
            cpa16(sb + TILE_B,     Aml + gk);
            cpa16(sb + 2 * TILE_B, Bnh + gk);
            cpa16(sb + 3 * TILE_B, Bnl + gk);
            asm volatile("cp.async.commit_group;" ::: "memory");
        }
    }

    float* out = g_gram[split];
    const int rbase = m0 + wr * 16 + (lane >> 2);
    const bool mirror = (m0 != n0);
#pragma unroll
    for (int nt = 0; nt < 4; nt++) {
        const int col = n0 + wc * 32 + nt * 8 + (lane & 3) * 2;
        *reinterpret_cast<float2*>(&out[(size_t)rbase * N + col]) =
            make_float2(acc[nt][0], acc[nt][1]);
        *reinterpret_cast<float2*>(&out[(size_t)(rbase + 8) * N + col]) =
            make_float2(acc[nt][2], acc[nt][3]);
        if (mirror) {
            out[(size_t)col * N + rbase]           = acc[nt][0];
            out[(size_t)(col + 1) * N + rbase]     = acc[nt][1];
            out[(size_t)col * N + rbase + 8]       = acc[nt][2];
            out[(size_t)(col + 1) * N + rbase + 8] = acc[nt][3];
        }
    }
}

// ---------------- kernel 3: warp-per-sample mining + DTW + final reduce ----------
// 256 blocks x 64 threads (2 warps). Warp w handles sample i = blockIdx*2 + w.
// Fully warp-synchronous until the final block-level counter step.
__global__ void __launch_bounds__(64)
mine_local_kernel(const void* __restrict__ targets_raw,
                  const float* __restrict__ LF,
                  float* __restrict__ out) {
    __shared__ float sbuf[2][3][PARTS][LSTRIDE];   // [warp][A/B/C][part][dim]
    __shared__ float dmat[2][2][PARTS][PARTS];     // [warp][AP/AN]
    __shared__ int   s_last;

    const int t    = threadIdx.x;
    const int w    = t >> 5;
    const int lane = t & 31;
    const int i    = blockIdx.x * 2 + w;

    // dtype detection: targets = j//4 -> word[5] nonzero for int32 layout, 0 for int64.
    const int* ip = reinterpret_cast<const int*>(targets_raw);
    const int stride = (ip[5] == 0) ? 2 : 1;

    const int   ti  = ip[(size_t)i * stride];
    const float sqi = g_sq[i];

    // ---- mining: each lane owns 16 consecutive j (ascending -> first-index) ----
    const int jb = lane * 16;
    float apv = -3.0e38f; int apj = N;
    float anv =  3.0e38f; int anj = N;

    float gsum[16];
#pragma unroll
    for (int q = 0; q < 4; q++) {
        float4 a = make_float4(0.f, 0.f, 0.f, 0.f);
#pragma unroll
        for (int s = 0; s < SPLITK; s++) {
            float4 v = *reinterpret_cast<const float4*>(
                &g_gram[s][(size_t)i * N + jb + q * 4]);
            a.x += v.x; a.y += v.y; a.z += v.z; a.w += v.w;
        }
        gsum[q * 4]     = a.x;
        gsum[q * 4 + 1] = a.y;
        gsum[q * 4 + 2] = a.z;
        gsum[q * 4 + 3] = a.w;
    }
#pragma unroll
    for (int u = 0; u < 16; u++) {
        const int j = jb + u;
        float d = sqrtf(fmaxf(sqi + g_sq[j] - 2.0f * gsum[u], 1e-12f));
        if (ip[(size_t)j * stride] == ti) {
            if (d > apv) { apv = d; apj = j; }
        } else {
            if (d < anv) { anv = d; anj = j; }
        }
    }
    // butterfly reduce -> all lanes hold the winners
#pragma unroll
    for (int o = 16; o > 0; o >>= 1) {
        float v = __shfl_xor_sync(0xffffffffu, apv, o);
        int   j = __shfl_xor_sync(0xffffffffu, apj, o);
        if (v > apv || (v == apv && j < apj)) { apv = v; apj = j; }
        v = __shfl_xor_sync(0xffffffffu, anv, o);
        j = __shfl_xor_sync(0xffffffffu, anj, o);
        if (v < anv || (v == anv && j < anj)) { anv = v; anj = j; }
    }
    if (lane == 0) g_gl[i] = fmaxf(0.0f, MARGIN + apv - anv);

    // ---- stage LF rows (i, apj, anj) into smem, transposed to [part][dim] ----
    const float* rows[3] = {
        LF + (size_t)i   * (LDIM * PARTS),
        LF + (size_t)apj * (LDIM * PARTS),
        LF + (size_t)anj * (LDIM * PARTS)
    };
#pragma unroll
    for (int rsel = 0; rsel < 3; rsel++) {
        const float4* src = reinterpret_cast<const float4*>(rows[rsel]);
#pragma unroll
        for (int k = 0; k < 8; k++) {
            const int f4 = lane + k * 32;       // float4 index 0..255
            float4 v = src[f4];
            const int e = f4 * 4;               // element = d*8 + p, p in {0|4}+0..3
            const int d = e >> 3, p0 = e & 7;
            sbuf[w][rsel][p0][d]     = v.x;
            sbuf[w][rsel][p0 + 1][d] = v.y;
            sbuf[w][rsel][p0 + 2][d] = v.z;
            sbuf[w][rsel][p0 + 3][d] = v.w;
        }
    }
    __syncwarp();

    // ---- part-distance matrices: lane -> (p, q) and (p+4, q), both AP and AN ----
    {
        const int p = lane >> 3, q = lane & 7;
        float s0 = 0.f, s1 = 0.f, s2 = 0.f, s3 = 0.f;
#pragma unroll 4
        for (int d = 0; d < LDIM; d++) {
            float a0 = sbuf[w][0][p][d];
            float a1 = sbuf[w][0][p + 4][d];
            float bq = sbuf[w][1][q][d];
            float cq = sbuf[w][2][q][d];
            float x0 = a0 - bq; s0 += x0 * x0;
            float x1 = a1 - bq; s1 += x1 * x1;
            float y0 = a0 - cq; s2 += y0 * y0;
            float y1 = a1 - cq; s3 += y1 * y1;
        }
        dmat[w][0][p][q]     = tanhf(0.5f * sqrtf(fmaxf(s0, 1e-12f)));
        dmat[w][0][p + 4][q] = tanhf(0.5f * sqrtf(fmaxf(s1, 1e-12f)));
        dmat[w][1][p][q]     = tanhf(0.5f * sqrtf(fmaxf(s2, 1e-12f)));
        dmat[w][1][p + 4][q] = tanhf(0.5f * sqrtf(fmaxf(s3, 1e-12f)));
    }
    __syncwarp();

    // ---- DTW shortest path: lane 0 -> AP matrix, lane 1 -> AN matrix ----
    float myres = 0.0f;
    if (lane < 2) {
        float (*dm)[PARTS] = dmat[w][lane];
        float prev[PARTS];
        prev[0] = 0.0f;
#pragma unroll
        for (int j = 1; j < PARTS; j++) prev[j] = 1e9f;
#pragma unroll
        for (int r = 0; r < PARTS; r++) {
            float left = 1e9f;
#pragma unroll
            for (int j = 0; j < PARTS; j++) {
                float cur = dm[r][j] + fminf(prev[j], left);
                prev[j] = cur;
                left = cur;
            }
        }
        myres = prev[PARTS - 1];
    }
    float res_an = __shfl_sync(0xffffffffu, myres, 1);
    if (lane == 0)
        g_ll[i] = fmaxf(0.0f, MARGIN + myres - res_an);

    // ---- last-block final reduction ----
    __syncthreads();
    if (t == 0) {
        __threadfence();
        int old = atomicAdd(&g_cnt, 1);
        s_last = (old == ML_BLOCKS - 1) ? 1 : 0;
    }
    __syncthreads();
    if (s_last) {
        if (t == 0) g_cnt = 0;       // reset for next graph replay
        float a = 0.0f, b = 0.0f;
#pragma unroll
        for (int j = t; j < N; j += 64) {
            a += g_gl[j];
            b += g_ll[j];
        }
#pragma unroll
        for (int o = 16; o > 0; o >>= 1) {
            a += __shfl_down_sync(0xffffffffu, a, o);
            b += __shfl_down_sync(0xffffffffu, b, o);
        }
        __shared__ float wa[2], wb[2];
        if (lane == 0) { wa[w] = a; wb[w] = b; }
        __syncthreads();
        if (t == 0) {
            out[0] = (wa[0] + wa[1]) * (1.0f / N);
            out[1] = (wb[0] + wb[1]) * (1.0f / N);
        }
    }
}

// ---------------- launch ----------------
extern "C" void kernel_launch(void* const* d_in, const int* in_sizes, int n_in,
                              void* d_out, int out_size) {
    const float* X  = (const float*)d_in[0];
    const void*  TG = d_in[1];
    const float* LF = (const float*)d_in[2];
    float* out = (float*)d_out;

    convert_kernel<<<N, 256>>>(X);
    gram_mma_kernel<<<dim3(NTILES, SPLITK), 256>>>();
    mine_local_kernel<<<ML_BLOCKS, 64>>>(TG, LF, out);
}